// round 12
// baseline (speedup 1.0000x reference)
#include <cuda_runtime.h>
#include <cuda_bf16.h>
#include <cstdint>
#include <cstddef>

// ---------------- problem constants ----------------
#define MAXM 8192
#define MAXN 4096
#define MAXK 4096

// quantized operands in device globals (allocation-free scratch)
// g_Xq holds (Xq - zp): exact integers in [-255,255], bf16-exact.
// g_Wq holds Wq:        exact integers in [-127,127], bf16-exact.
__device__ __nv_bfloat16 g_Xq[(size_t)MAXM * MAXK];
__device__ __nv_bfloat16 g_Wq[(size_t)MAXN * MAXK];
__device__ float g_xs[MAXM];   // activation scale per token
__device__ float g_ws[MAXN];   // weight scale per row

// ---------------- helpers ----------------
__device__ __forceinline__ uint32_t smem_u32(const void* p) {
    return (uint32_t)__cvta_generic_to_shared(p);
}
__device__ __forceinline__ void cp16(uint32_t dst, const void* src) {
    asm volatile("cp.async.cg.shared.global [%0], [%1], 16;"
                 :: "r"(dst), "l"(__cvta_generic_to_global(src)) : "memory");
}
__device__ __forceinline__ void cp_commit() {
    asm volatile("cp.async.commit_group;" ::: "memory");
}
template <int N>
__device__ __forceinline__ void cp_wait_group() {
    asm volatile("cp.async.wait_group %0;" :: "n"(N) : "memory");
}
__device__ __forceinline__ void ldsm4(uint32_t& r0, uint32_t& r1, uint32_t& r2,
                                      uint32_t& r3, uint32_t addr) {
    asm volatile("ldmatrix.sync.aligned.m8n8.x4.shared.b16 {%0,%1,%2,%3}, [%4];"
                 : "=r"(r0), "=r"(r1), "=r"(r2), "=r"(r3) : "r"(addr));
}
__device__ __forceinline__ void hmma16816(float* d, const uint32_t* a,
                                          uint32_t b0, uint32_t b1) {
    asm volatile(
        "mma.sync.aligned.m16n8k16.row.col.f32.bf16.bf16.f32 "
        "{%0,%1,%2,%3}, {%4,%5,%6,%7}, {%8,%9}, {%0,%1,%2,%3};"
        : "+f"(d[0]), "+f"(d[1]), "+f"(d[2]), "+f"(d[3])
        : "r"(a[0]), "r"(a[1]), "r"(a[2]), "r"(a[3]), "r"(b0), "r"(b1));
}

// ---------------- block reductions ----------------
__device__ __forceinline__ float blockReduceMaxF(float v) {
    __shared__ float sh[8];
    #pragma unroll
    for (int o = 16; o; o >>= 1) v = fmaxf(v, __shfl_xor_sync(0xffffffffu, v, o));
    int wid = threadIdx.x >> 5, lid = threadIdx.x & 31;
    if (lid == 0) sh[wid] = v;
    __syncthreads();
    if (threadIdx.x < 32) {
        float t = (lid < 8) ? sh[lid] : -3.4e38f;
        #pragma unroll
        for (int o = 4; o; o >>= 1) t = fmaxf(t, __shfl_xor_sync(0xffffffffu, t, o));
        if (lid == 0) sh[0] = t;
    }
    __syncthreads();
    float r = sh[0];
    __syncthreads();
    return r;
}

// ---------------- fused quantization kernel ----------------
// blocks [0, N)        : quantize weight row n
// blocks [N, N + M)    : quantize activation row m
__global__ void __launch_bounds__(256) quant_fused_kernel(
    const float* __restrict__ W, const float* __restrict__ X, int K, int N) {
    int b = blockIdx.x;
    if (b < N) {
        int n = b;
        const float4* row = (const float4*)(W + (size_t)n * K);
        int nv = K >> 2;
        float amax = 0.f;
        for (int i = threadIdx.x; i < nv; i += blockDim.x) {
            float4 v = row[i];
            amax = fmaxf(amax, fmaxf(fmaxf(fabsf(v.x), fabsf(v.y)),
                                     fmaxf(fabsf(v.z), fabsf(v.w))));
        }
        amax = blockReduceMaxF(amax);
        float scale = (amax > 0.f) ? (amax / 127.0f) : 1.0f;
        if (threadIdx.x == 0) g_ws[n] = scale;
        __nv_bfloat16* o = g_Wq + (size_t)n * K;
        for (int i = threadIdx.x; i < nv; i += blockDim.x) {
            float4 v = row[i];
            float q0 = fminf(fmaxf(rintf(v.x / scale), -127.f), 127.f);
            float q1 = fminf(fmaxf(rintf(v.y / scale), -127.f), 127.f);
            float q2 = fminf(fmaxf(rintf(v.z / scale), -127.f), 127.f);
            float q3 = fminf(fmaxf(rintf(v.w / scale), -127.f), 127.f);
            uint2 u;
            u.x = ((uint32_t)__bfloat16_as_ushort(__float2bfloat16(q1)) << 16) |
                   (uint32_t)__bfloat16_as_ushort(__float2bfloat16(q0));
            u.y = ((uint32_t)__bfloat16_as_ushort(__float2bfloat16(q3)) << 16) |
                   (uint32_t)__bfloat16_as_ushort(__float2bfloat16(q2));
            *reinterpret_cast<uint2*>(o + 4 * (size_t)i) = u;
        }
    } else {
        int m = b - N;
        const float4* row = (const float4*)(X + (size_t)m * K);
        int nv = K >> 2;
        float vmax = -3.4e38f, nvmin = -3.4e38f;  // nvmin = max(-x)
        for (int i = threadIdx.x; i < nv; i += blockDim.x) {
            float4 v = row[i];
            vmax  = fmaxf(vmax,  fmaxf(fmaxf(v.x, v.y), fmaxf(v.z, v.w)));
            nvmin = fmaxf(nvmin, fmaxf(fmaxf(-v.x, -v.y), fmaxf(-v.z, -v.w)));
        }
        vmax  = blockReduceMaxF(vmax);
        nvmin = blockReduceMaxF(nvmin);
        float vmin = -nvmin;
        float rng = vmax - vmin;
        float scale = (rng > 0.f) ? (rng / 255.0f) : 1.0f;
        float zp = rintf(-vmin / scale);
        if (threadIdx.x == 0) g_xs[m] = scale;
        __nv_bfloat16* o = g_Xq + (size_t)m * K;
        for (int i = threadIdx.x; i < nv; i += blockDim.x) {
            float4 v = row[i];
            float q0 = fminf(fmaxf(rintf(v.x / scale) + zp, 0.f), 255.f) - zp;
            float q1 = fminf(fmaxf(rintf(v.y / scale) + zp, 0.f), 255.f) - zp;
            float q2 = fminf(fmaxf(rintf(v.z / scale) + zp, 0.f), 255.f) - zp;
            float q3 = fminf(fmaxf(rintf(v.w / scale) + zp, 0.f), 255.f) - zp;
            uint2 u;
            u.x = ((uint32_t)__bfloat16_as_ushort(__float2bfloat16(q1)) << 16) |
                   (uint32_t)__bfloat16_as_ushort(__float2bfloat16(q0));
            u.y = ((uint32_t)__bfloat16_as_ushort(__float2bfloat16(q3)) << 16) |
                   (uint32_t)__bfloat16_as_ushort(__float2bfloat16(q2));
            *reinterpret_cast<uint2*>(o + 4 * (size_t)i) = u;
        }
    }
}

// ---------------- bf16 GEMM (HMMA via mma.sync), 512 threads ----------------
#define BM 256
#define BN 256
#define BK 64                          // bf16 elems per K-chunk = 128 bytes/row
#define STAGES 3
#define AS_BYTES (BM * 128)            // 32 KB
#define BS_BYTES (BN * 128)            // 32 KB
#define STAGE_BYTES (AS_BYTES + BS_BYTES)   // 64 KB
#define GEMM_SMEM (STAGES * STAGE_BYTES)    // 192 KB

__device__ __forceinline__ void load_stage_bf16(uint32_t smem_base, int s, int kc,
                                                int m_base, int n_base, int K, int tid) {
    uint32_t a_smem = smem_base + s * STAGE_BYTES;
    uint32_t b_smem = a_smem + AS_BYTES;
    const char* Abase = (const char*)g_Xq;
    const char* Bbase = (const char*)g_Wq;
    size_t koff = (size_t)kc * BK * 2;     // bytes
    // A: 256 rows x 8 x 16B = 2048 chunks / 512 threads = 4 each
    #pragma unroll
    for (int it = 0; it < 4; it++) {
        int c = tid + it * 512;
        int row = c >> 3, ch = c & 7;
        const void* src = Abase + ((size_t)(m_base + row) * K) * 2 + koff + ch * 16;
        cp16(a_smem + row * 128 + ((ch ^ (row & 7)) * 16), src);
    }
    // B: 256 rows x 8 x 16B = 2048 chunks / 512 threads = 4 each
    #pragma unroll
    for (int it = 0; it < 4; it++) {
        int c = tid + it * 512;
        int row = c >> 3, ch = c & 7;
        const void* src = Bbase + ((size_t)(n_base + row) * K) * 2 + koff + ch * 16;
        cp16(b_smem + row * 128 + ((ch ^ (row & 7)) * 16), src);
    }
}

__global__ void __launch_bounds__(512, 1)
qgemm_kernel(const float* __restrict__ bias, float* __restrict__ out,
             int M, int N, int K) {
    extern __shared__ char smem[];
    const int tid  = threadIdx.x;
    const int wid  = tid >> 5;
    const int lane = tid & 31;
    const int wm   = wid >> 2;        // 0..3  (64-row slab)
    const int wn   = wid & 3;         // 0..3  (64-col slab)
    uint32_t smem_base = smem_u32(smem);

    const int m_base = blockIdx.y * BM;
    const int n_base = blockIdx.x * BN;

    float acc[4][8][4];               // [mt][nt][reg], nt = n8 block 0..7
    #pragma unroll
    for (int mt = 0; mt < 4; mt++)
        #pragma unroll
        for (int nt = 0; nt < 8; nt++)
            #pragma unroll
            for (int r = 0; r < 4; r++) acc[mt][nt][r] = 0.f;

    const int iters = K / BK;         // 64

    // per-thread invariant addressing
    const int rowA  = wm * 64 + (lane & 15);   // + mt*16
    const int halfA = lane >> 4;               // 16B chunk low bit (k half)
    const int swzA  = rowA & 7;
    const int rowB0 = wn * 64 + (lane & 15);   // + nq*16
    const int swzB  = lane & 7;

    #pragma unroll
    for (int i = 0; i < STAGES - 1; i++) {
        load_stage_bf16(smem_base, i, i, m_base, n_base, K, tid);
        cp_commit();
    }

    for (int i = 0; i < iters; i++) {
        int s = i % STAGES;
        cp_wait_group<STAGES - 2>();
        __syncthreads();

        // Issue next-stage cp.async first so it's shadowed by this chunk's MMAs.
        int j = i + STAGES - 1;
        if (j < iters)
            load_stage_bf16(smem_base, j % STAGES, j, m_base, n_base, K, tid);
        cp_commit();

        uint32_t a_base = smem_base + s * STAGE_BYTES;
        uint32_t b_base = a_base + AS_BYTES;

        #pragma unroll
        for (int ks = 0; ks < 4; ks++) {
            // B: 4 ldsm.x4 covering n64 at this k16 step
            uint32_t bq[4][4];
            #pragma unroll
            for (int nq = 0; nq < 4; nq++)
                ldsm4(bq[nq][0], bq[nq][1], bq[nq][2], bq[nq][3],
                      b_base + (rowB0 + nq * 16) * 128 +
                      (((2 * ks + halfA) ^ swzB) * 16));
            #pragma unroll
            for (int mt = 0; mt < 4; mt++) {
                uint32_t a[4];
                ldsm4(a[0], a[1], a[2], a[3],
                      a_base + (rowA + mt * 16) * 128 +
                      (((2 * ks + halfA) ^ swzA) * 16));
                #pragma unroll
                for (int nq = 0; nq < 4; nq++) {
                    hmma16816(acc[mt][nq * 2 + 0], a, bq[nq][0], bq[nq][2]);
                    hmma16816(acc[mt][nq * 2 + 1], a, bq[nq][1], bq[nq][3]);
                }
            }
        }
    }

    // ---------------- epilogue ----------------
    #pragma unroll
    for (int mt = 0; mt < 4; mt++) {
        #pragma unroll
        for (int p = 0; p < 2; p++) {
            int m = m_base + wm * 64 + mt * 16 + (lane >> 2) + p * 8;
            float cs = g_xs[m];
            float* orow = out + (size_t)m * N + n_base + wn * 64;
            #pragma unroll
            for (int nt = 0; nt < 8; nt++) {
                int nc = nt * 8 + (lane & 3) * 2;
                int n  = n_base + wn * 64 + nc;
                float2 o;
                o.x = acc[mt][nt][p * 2 + 0] * (cs * g_ws[n + 0]) + bias[n + 0];
                o.y = acc[mt][nt][p * 2 + 1] * (cs * g_ws[n + 1]) + bias[n + 1];
                *reinterpret_cast<float2*>(orow + nc) = o;
            }
        }
    }
}

// ---------------- launcher ----------------
extern "C" void kernel_launch(void* const* d_in, const int* in_sizes, int n_in,
                              void* d_out, int out_size) {
    const float* x    = (const float*)d_in[0];
    const float* w    = (const float*)d_in[1];
    const float* bias = (const float*)d_in[2];
    int N = in_sizes[2];                  // 4096
    int K = in_sizes[1] / N;              // 4096
    int M = in_sizes[0] / K;              // 8192

    quant_fused_kernel<<<N + M, 256>>>(w, x, K, N);

    cudaFuncSetAttribute(qgemm_kernel, cudaFuncAttributeMaxDynamicSharedMemorySize,
                         GEMM_SMEM);
    dim3 grid(N / BN, M / BM);
    qgemm_kernel<<<grid, 512, GEMM_SMEM>>>(bias, (float*)d_out, M, N, K);
}

// round 13
// speedup vs baseline: 3.8225x; 3.8225x over previous
#include <cuda_runtime.h>
#include <cuda_bf16.h>
#include <cstdint>
#include <cstddef>

// ---------------- problem constants ----------------
#define MAXM 8192
#define MAXN 4096
#define MAXK 4096

// quantized operands in device globals (allocation-free scratch)
// g_Xq holds (Xq - zp): exact integers in [-255,255], bf16-exact.
// g_Wq holds Wq:        exact integers in [-127,127], bf16-exact.
__device__ __nv_bfloat16 g_Xq[(size_t)MAXM * MAXK];
__device__ __nv_bfloat16 g_Wq[(size_t)MAXN * MAXK];
__device__ float g_xs[MAXM];   // activation scale per token
__device__ float g_ws[MAXN];   // weight scale per row

// ---------------- helpers ----------------
__device__ __forceinline__ uint32_t smem_u32(const void* p) {
    return (uint32_t)__cvta_generic_to_shared(p);
}
__device__ __forceinline__ void cp16(uint32_t dst, const void* src) {
    asm volatile("cp.async.cg.shared.global [%0], [%1], 16;"
                 :: "r"(dst), "l"(__cvta_generic_to_global(src)) : "memory");
}
__device__ __forceinline__ void cp_commit() {
    asm volatile("cp.async.commit_group;" ::: "memory");
}
template <int N>
__device__ __forceinline__ void cp_wait_group() {
    asm volatile("cp.async.wait_group %0;" :: "n"(N) : "memory");
}
__device__ __forceinline__ void ldsm4(uint32_t& r0, uint32_t& r1, uint32_t& r2,
                                      uint32_t& r3, uint32_t addr) {
    asm volatile("ldmatrix.sync.aligned.m8n8.x4.shared.b16 {%0,%1,%2,%3}, [%4];"
                 : "=r"(r0), "=r"(r1), "=r"(r2), "=r"(r3) : "r"(addr));
}
__device__ __forceinline__ void hmma16816(float* d, const uint32_t* a,
                                          uint32_t b0, uint32_t b1) {
    asm volatile(
        "mma.sync.aligned.m16n8k16.row.col.f32.bf16.bf16.f32 "
        "{%0,%1,%2,%3}, {%4,%5,%6,%7}, {%8,%9}, {%0,%1,%2,%3};"
        : "+f"(d[0]), "+f"(d[1]), "+f"(d[2]), "+f"(d[3])
        : "r"(a[0]), "r"(a[1]), "r"(a[2]), "r"(a[3]), "r"(b0), "r"(b1));
}

// ---------------- block reductions ----------------
__device__ __forceinline__ float blockReduceMaxF(float v) {
    __shared__ float sh[8];
    #pragma unroll
    for (int o = 16; o; o >>= 1) v = fmaxf(v, __shfl_xor_sync(0xffffffffu, v, o));
    int wid = threadIdx.x >> 5, lid = threadIdx.x & 31;
    if (lid == 0) sh[wid] = v;
    __syncthreads();
    if (threadIdx.x < 32) {
        float t = (lid < 8) ? sh[lid] : -3.4e38f;
        #pragma unroll
        for (int o = 4; o; o >>= 1) t = fmaxf(t, __shfl_xor_sync(0xffffffffu, t, o));
        if (lid == 0) sh[0] = t;
    }
    __syncthreads();
    float r = sh[0];
    __syncthreads();
    return r;
}

// ---------------- fused quantization kernel ----------------
// blocks [0, N)        : quantize weight row n
// blocks [N, N + M)    : quantize activation row m
__global__ void __launch_bounds__(256) quant_fused_kernel(
    const float* __restrict__ W, const float* __restrict__ X, int K, int N) {
    int b = blockIdx.x;
    if (b < N) {
        int n = b;
        const float4* row = (const float4*)(W + (size_t)n * K);
        int nv = K >> 2;
        float amax = 0.f;
        for (int i = threadIdx.x; i < nv; i += blockDim.x) {
            float4 v = row[i];
            amax = fmaxf(amax, fmaxf(fmaxf(fabsf(v.x), fabsf(v.y)),
                                     fmaxf(fabsf(v.z), fabsf(v.w))));
        }
        amax = blockReduceMaxF(amax);
        float scale = (amax > 0.f) ? (amax / 127.0f) : 1.0f;
        if (threadIdx.x == 0) g_ws[n] = scale;
        __nv_bfloat16* o = g_Wq + (size_t)n * K;
        for (int i = threadIdx.x; i < nv; i += blockDim.x) {
            float4 v = row[i];
            float q0 = fminf(fmaxf(rintf(v.x / scale), -127.f), 127.f);
            float q1 = fminf(fmaxf(rintf(v.y / scale), -127.f), 127.f);
            float q2 = fminf(fmaxf(rintf(v.z / scale), -127.f), 127.f);
            float q3 = fminf(fmaxf(rintf(v.w / scale), -127.f), 127.f);
            uint2 u;
            u.x = ((uint32_t)__bfloat16_as_ushort(__float2bfloat16(q1)) << 16) |
                   (uint32_t)__bfloat16_as_ushort(__float2bfloat16(q0));
            u.y = ((uint32_t)__bfloat16_as_ushort(__float2bfloat16(q3)) << 16) |
                   (uint32_t)__bfloat16_as_ushort(__float2bfloat16(q2));
            *reinterpret_cast<uint2*>(o + 4 * (size_t)i) = u;
        }
    } else {
        int m = b - N;
        const float4* row = (const float4*)(X + (size_t)m * K);
        int nv = K >> 2;
        float vmax = -3.4e38f, nvmin = -3.4e38f;  // nvmin = max(-x)
        for (int i = threadIdx.x; i < nv; i += blockDim.x) {
            float4 v = row[i];
            vmax  = fmaxf(vmax,  fmaxf(fmaxf(v.x, v.y), fmaxf(v.z, v.w)));
            nvmin = fmaxf(nvmin, fmaxf(fmaxf(-v.x, -v.y), fmaxf(-v.z, -v.w)));
        }
        vmax  = blockReduceMaxF(vmax);
        nvmin = blockReduceMaxF(nvmin);
        float vmin = -nvmin;
        float rng = vmax - vmin;
        float scale = (rng > 0.f) ? (rng / 255.0f) : 1.0f;
        float zp = rintf(-vmin / scale);
        if (threadIdx.x == 0) g_xs[m] = scale;
        __nv_bfloat16* o = g_Xq + (size_t)m * K;
        for (int i = threadIdx.x; i < nv; i += blockDim.x) {
            float4 v = row[i];
            float q0 = fminf(fmaxf(rintf(v.x / scale) + zp, 0.f), 255.f) - zp;
            float q1 = fminf(fmaxf(rintf(v.y / scale) + zp, 0.f), 255.f) - zp;
            float q2 = fminf(fmaxf(rintf(v.z / scale) + zp, 0.f), 255.f) - zp;
            float q3 = fminf(fmaxf(rintf(v.w / scale) + zp, 0.f), 255.f) - zp;
            uint2 u;
            u.x = ((uint32_t)__bfloat16_as_ushort(__float2bfloat16(q1)) << 16) |
                   (uint32_t)__bfloat16_as_ushort(__float2bfloat16(q0));
            u.y = ((uint32_t)__bfloat16_as_ushort(__float2bfloat16(q3)) << 16) |
                   (uint32_t)__bfloat16_as_ushort(__float2bfloat16(q2));
            *reinterpret_cast<uint2*>(o + 4 * (size_t)i) = u;
        }
    }
}

// ---------------- bf16 GEMM: 512 threads, 128x256 tile, warp tile 32x64 ----
#define BM 128
#define BN 256
#define BK 64                          // bf16 elems per K-chunk = 128 bytes/row
#define STAGES 3
#define AS_BYTES (BM * 128)            // 16 KB
#define BS_BYTES (BN * 128)            // 32 KB
#define STAGE_BYTES (AS_BYTES + BS_BYTES)   // 48 KB
#define GEMM_SMEM (STAGES * STAGE_BYTES)    // 144 KB

__device__ __forceinline__ void load_stage_bf16(uint32_t smem_base, int s, int kc,
                                                int m_base, int n_base, int K, int tid) {
    uint32_t a_smem = smem_base + s * STAGE_BYTES;
    uint32_t b_smem = a_smem + AS_BYTES;
    const char* Abase = (const char*)g_Xq;
    const char* Bbase = (const char*)g_Wq;
    size_t koff = (size_t)kc * BK * 2;     // bytes
    // A: 128 rows x 8 x 16B = 1024 chunks / 512 threads = 2 each
    #pragma unroll
    for (int it = 0; it < 2; it++) {
        int c = tid + it * 512;
        int row = c >> 3, ch = c & 7;
        const void* src = Abase + ((size_t)(m_base + row) * K) * 2 + koff + ch * 16;
        cp16(a_smem + row * 128 + ((ch ^ (row & 7)) * 16), src);
    }
    // B: 256 rows x 8 x 16B = 2048 chunks / 512 threads = 4 each
    #pragma unroll
    for (int it = 0; it < 4; it++) {
        int c = tid + it * 512;
        int row = c >> 3, ch = c & 7;
        const void* src = Bbase + ((size_t)(n_base + row) * K) * 2 + koff + ch * 16;
        cp16(b_smem + row * 128 + ((ch ^ (row & 7)) * 16), src);
    }
}

__global__ void __launch_bounds__(512, 1)
qgemm_kernel(const float* __restrict__ bias, float* __restrict__ out,
             int M, int N, int K) {
    extern __shared__ char smem[];
    const int tid  = threadIdx.x;
    const int wid  = tid >> 5;
    const int lane = tid & 31;
    const int wm   = wid >> 2;        // 0..3  (32-row slab)
    const int wn   = wid & 3;         // 0..3  (64-col slab)
    uint32_t smem_base = smem_u32(smem);

    const int m_base = blockIdx.y * BM;
    const int n_base = blockIdx.x * BN;

    float acc[2][8][4];               // [mt][nt][reg]: 64 regs
    #pragma unroll
    for (int mt = 0; mt < 2; mt++)
        #pragma unroll
        for (int nt = 0; nt < 8; nt++)
            #pragma unroll
            for (int r = 0; r < 4; r++) acc[mt][nt][r] = 0.f;

    const int iters = K / BK;         // 64

    // per-thread invariant addressing
    const int rowA  = wm * 32 + (lane & 15);   // + mt*16
    const int halfA = lane >> 4;               // 16B chunk low bit (k half)
    const int swzA  = rowA & 7;
    const int rowB0 = wn * 64 + (lane & 15);   // + nq*16
    const int swzB  = lane & 7;

    #pragma unroll
    for (int i = 0; i < STAGES - 1; i++) {
        load_stage_bf16(smem_base, i, i, m_base, n_base, K, tid);
        cp_commit();
    }

    for (int i = 0; i < iters; i++) {
        int s = i % STAGES;
        cp_wait_group<STAGES - 2>();
        __syncthreads();

        // Issue next-stage cp.async first so it's shadowed by this chunk's MMAs.
        int j = i + STAGES - 1;
        if (j < iters)
            load_stage_bf16(smem_base, j % STAGES, j, m_base, n_base, K, tid);
        cp_commit();

        uint32_t a_base = smem_base + s * STAGE_BYTES;
        uint32_t b_base = a_base + AS_BYTES;

        #pragma unroll
        for (int ks = 0; ks < 4; ks++) {
            // B: 4 ldsm.x4 covering n64 at this k16 step
            uint32_t bq[4][4];
            #pragma unroll
            for (int nq = 0; nq < 4; nq++)
                ldsm4(bq[nq][0], bq[nq][1], bq[nq][2], bq[nq][3],
                      b_base + (rowB0 + nq * 16) * 128 +
                      (((2 * ks + halfA) ^ swzB) * 16));
            #pragma unroll
            for (int mt = 0; mt < 2; mt++) {
                uint32_t a[4];
                ldsm4(a[0], a[1], a[2], a[3],
                      a_base + (rowA + mt * 16) * 128 +
                      (((2 * ks + halfA) ^ swzA) * 16));
                #pragma unroll
                for (int nq = 0; nq < 4; nq++) {
                    hmma16816(acc[mt][nq * 2 + 0], a, bq[nq][0], bq[nq][2]);
                    hmma16816(acc[mt][nq * 2 + 1], a, bq[nq][1], bq[nq][3]);
                }
            }
        }
    }

    // ---------------- epilogue ----------------
    #pragma unroll
    for (int mt = 0; mt < 2; mt++) {
        #pragma unroll
        for (int p = 0; p < 2; p++) {
            int m = m_base + wm * 32 + mt * 16 + (lane >> 2) + p * 8;
            float cs = g_xs[m];
            float* orow = out + (size_t)m * N + n_base + wn * 64;
            #pragma unroll
            for (int nt = 0; nt < 8; nt++) {
                int nc = nt * 8 + (lane & 3) * 2;
                int n  = n_base + wn * 64 + nc;
                float2 o;
                o.x = acc[mt][nt][p * 2 + 0] * (cs * g_ws[n + 0]) + bias[n + 0];
                o.y = acc[mt][nt][p * 2 + 1] * (cs * g_ws[n + 1]) + bias[n + 1];
                *reinterpret_cast<float2*>(orow + nc) = o;
            }
        }
    }
}

// ---------------- launcher ----------------
extern "C" void kernel_launch(void* const* d_in, const int* in_sizes, int n_in,
                              void* d_out, int out_size) {
    const float* x    = (const float*)d_in[0];
    const float* w    = (const float*)d_in[1];
    const float* bias = (const float*)d_in[2];
    int N = in_sizes[2];                  // 4096
    int K = in_sizes[1] / N;              // 4096
    int M = in_sizes[0] / K;              // 8192

    quant_fused_kernel<<<N + M, 256>>>(w, x, K, N);

    cudaFuncSetAttribute(qgemm_kernel, cudaFuncAttributeMaxDynamicSharedMemorySize,
                         GEMM_SMEM);
    dim3 grid(N / BN, M / BM);
    qgemm_kernel<<<grid, 512, GEMM_SMEM>>>(bias, (float*)d_out, M, N, K);
}

// round 14
// speedup vs baseline: 3.8779x; 1.0145x over previous
#include <cuda_runtime.h>
#include <cuda_bf16.h>
#include <cstdint>
#include <cstddef>

// ---------------- problem constants ----------------
#define MAXM 8192
#define MAXN 4096
#define MAXK 4096

// quantized operands in device globals (allocation-free scratch)
__device__ __nv_bfloat16 g_Xq[(size_t)MAXM * MAXK];   // (Xq - zp), |v|<=255
__device__ __nv_bfloat16 g_Wq[(size_t)MAXN * MAXK];   // Wq, |v|<=127
__device__ float g_xs[MAXM];   // activation scale per token
__device__ float g_ws[MAXN];   // weight scale per row

// ---------------- helpers ----------------
__device__ __forceinline__ uint32_t smem_u32(const void* p) {
    return (uint32_t)__cvta_generic_to_shared(p);
}
__device__ __forceinline__ void cp16(uint32_t dst, const void* src) {
    asm volatile("cp.async.cg.shared.global [%0], [%1], 16;"
                 :: "r"(dst), "l"(__cvta_generic_to_global(src)) : "memory");
}
__device__ __forceinline__ void cp_commit() {
    asm volatile("cp.async.commit_group;" ::: "memory");
}
template <int N>
__device__ __forceinline__ void cp_wait_group() {
    asm volatile("cp.async.wait_group %0;" :: "n"(N) : "memory");
}
__device__ __forceinline__ void ldsm4(uint32_t& r0, uint32_t& r1, uint32_t& r2,
                                      uint32_t& r3, uint32_t addr) {
    asm volatile("ldmatrix.sync.aligned.m8n8.x4.shared.b16 {%0,%1,%2,%3}, [%4];"
                 : "=r"(r0), "=r"(r1), "=r"(r2), "=r"(r3) : "r"(addr));
}
__device__ __forceinline__ void hmma16816(float* d, const uint32_t* a,
                                          uint32_t b0, uint32_t b1) {
    asm volatile(
        "mma.sync.aligned.m16n8k16.row.col.f32.bf16.bf16.f32 "
        "{%0,%1,%2,%3}, {%4,%5,%6,%7}, {%8,%9}, {%0,%1,%2,%3};"
        : "+f"(d[0]), "+f"(d[1]), "+f"(d[2]), "+f"(d[3])
        : "r"(a[0]), "r"(a[1]), "r"(a[2]), "r"(a[3]), "r"(b0), "r"(b1));
}

// ---------------- block reductions ----------------
__device__ __forceinline__ float blockReduceMaxF(float v) {
    __shared__ float sh[8];
    #pragma unroll
    for (int o = 16; o; o >>= 1) v = fmaxf(v, __shfl_xor_sync(0xffffffffu, v, o));
    int wid = threadIdx.x >> 5, lid = threadIdx.x & 31;
    if (lid == 0) sh[wid] = v;
    __syncthreads();
    if (threadIdx.x < 32) {
        float t = (lid < 8) ? sh[lid] : -3.4e38f;
        #pragma unroll
        for (int o = 4; o; o >>= 1) t = fmaxf(t, __shfl_xor_sync(0xffffffffu, t, o));
        if (lid == 0) sh[0] = t;
    }
    __syncthreads();
    float r = sh[0];
    __syncthreads();
    return r;
}

// ---------------- fused quantization kernel ----------------
__global__ void __launch_bounds__(256) quant_fused_kernel(
    const float* __restrict__ W, const float* __restrict__ X, int K, int N) {
    int b = blockIdx.x;
    if (b < N) {
        int n = b;
        const float4* row = (const float4*)(W + (size_t)n * K);
        int nv = K >> 2;
        float amax = 0.f;
        for (int i = threadIdx.x; i < nv; i += blockDim.x) {
            float4 v = row[i];
            amax = fmaxf(amax, fmaxf(fmaxf(fabsf(v.x), fabsf(v.y)),
                                     fmaxf(fabsf(v.z), fabsf(v.w))));
        }
        amax = blockReduceMaxF(amax);
        float scale = (amax > 0.f) ? (amax / 127.0f) : 1.0f;
        if (threadIdx.x == 0) g_ws[n] = scale;
        __nv_bfloat16* o = g_Wq + (size_t)n * K;
        for (int i = threadIdx.x; i < nv; i += blockDim.x) {
            float4 v = row[i];
            float q0 = fminf(fmaxf(rintf(v.x / scale), -127.f), 127.f);
            float q1 = fminf(fmaxf(rintf(v.y / scale), -127.f), 127.f);
            float q2 = fminf(fmaxf(rintf(v.z / scale), -127.f), 127.f);
            float q3 = fminf(fmaxf(rintf(v.w / scale), -127.f), 127.f);
            uint2 u;
            u.x = ((uint32_t)__bfloat16_as_ushort(__float2bfloat16(q1)) << 16) |
                   (uint32_t)__bfloat16_as_ushort(__float2bfloat16(q0));
            u.y = ((uint32_t)__bfloat16_as_ushort(__float2bfloat16(q3)) << 16) |
                   (uint32_t)__bfloat16_as_ushort(__float2bfloat16(q2));
            *reinterpret_cast<uint2*>(o + 4 * (size_t)i) = u;
        }
    } else {
        int m = b - N;
        const float4* row = (const float4*)(X + (size_t)m * K);
        int nv = K >> 2;
        float vmax = -3.4e38f, nvmin = -3.4e38f;
        for (int i = threadIdx.x; i < nv; i += blockDim.x) {
            float4 v = row[i];
            vmax  = fmaxf(vmax,  fmaxf(fmaxf(v.x, v.y), fmaxf(v.z, v.w)));
            nvmin = fmaxf(nvmin, fmaxf(fmaxf(-v.x, -v.y), fmaxf(-v.z, -v.w)));
        }
        vmax  = blockReduceMaxF(vmax);
        nvmin = blockReduceMaxF(nvmin);
        float vmin = -nvmin;
        float rng = vmax - vmin;
        float scale = (rng > 0.f) ? (rng / 255.0f) : 1.0f;
        float zp = rintf(-vmin / scale);
        if (threadIdx.x == 0) g_xs[m] = scale;
        __nv_bfloat16* o = g_Xq + (size_t)m * K;
        for (int i = threadIdx.x; i < nv; i += blockDim.x) {
            float4 v = row[i];
            float q0 = fminf(fmaxf(rintf(v.x / scale) + zp, 0.f), 255.f) - zp;
            float q1 = fminf(fmaxf(rintf(v.y / scale) + zp, 0.f), 255.f) - zp;
            float q2 = fminf(fmaxf(rintf(v.z / scale) + zp, 0.f), 255.f) - zp;
            float q3 = fminf(fmaxf(rintf(v.w / scale) + zp, 0.f), 255.f) - zp;
            uint2 u;
            u.x = ((uint32_t)__bfloat16_as_ushort(__float2bfloat16(q1)) << 16) |
                   (uint32_t)__bfloat16_as_ushort(__float2bfloat16(q0));
            u.y = ((uint32_t)__bfloat16_as_ushort(__float2bfloat16(q3)) << 16) |
                   (uint32_t)__bfloat16_as_ushort(__float2bfloat16(q2));
            *reinterpret_cast<uint2*>(o + 4 * (size_t)i) = u;
        }
    }
}

// ------- bf16 GEMM: 512 thr, 128x256 tile, warp 32x64, 4 stages, 2-chunk sync --
#define BM 128
#define BN 256
#define BK 64                          // bf16 elems per K-chunk = 128 bytes/row
#define STAGES 4
#define AS_BYTES (BM * 128)            // 16 KB
#define BS_BYTES (BN * 128)            // 32 KB
#define STAGE_BYTES (AS_BYTES + BS_BYTES)   // 48 KB
#define GEMM_SMEM (STAGES * STAGE_BYTES)    // 192 KB

__device__ __forceinline__ void load_stage_bf16(uint32_t smem_base, int s, int kc,
                                                int m_base, int n_base, int K, int tid) {
    uint32_t a_smem = smem_base + s * STAGE_BYTES;
    uint32_t b_smem = a_smem + AS_BYTES;
    const char* Abase = (const char*)g_Xq;
    const char* Bbase = (const char*)g_Wq;
    size_t koff = (size_t)kc * BK * 2;     // bytes
    // A: 128 rows x 8 x 16B = 1024 chunks / 512 threads = 2 each
    #pragma unroll
    for (int it = 0; it < 2; it++) {
        int c = tid + it * 512;
        int row = c >> 3, ch = c & 7;
        const void* src = Abase + ((size_t)(m_base + row) * K) * 2 + koff + ch * 16;
        cp16(a_smem + row * 128 + ((ch ^ (row & 7)) * 16), src);
    }
    // B: 256 rows x 8 x 16B = 2048 chunks / 512 threads = 4 each
    #pragma unroll
    for (int it = 0; it < 4; it++) {
        int c = tid + it * 512;
        int row = c >> 3, ch = c & 7;
        const void* src = Bbase + ((size_t)(n_base + row) * K) * 2 + koff + ch * 16;
        cp16(b_smem + row * 128 + ((ch ^ (row & 7)) * 16), src);
    }
}

__global__ void __launch_bounds__(512, 1)
qgemm_kernel(const float* __restrict__ bias, float* __restrict__ out,
             int M, int N, int K) {
    extern __shared__ char smem[];
    const int tid  = threadIdx.x;
    const int wid  = tid >> 5;
    const int lane = tid & 31;
    const int wm   = wid >> 2;        // 0..3  (32-row slab)
    const int wn   = wid & 3;         // 0..3  (64-col slab)
    uint32_t smem_base = smem_u32(smem);

    const int m_base = blockIdx.y * BM;
    const int n_base = blockIdx.x * BN;

    float acc[2][8][4];               // 64 regs
    #pragma unroll
    for (int mt = 0; mt < 2; mt++)
        #pragma unroll
        for (int nt = 0; nt < 8; nt++)
            #pragma unroll
            for (int r = 0; r < 4; r++) acc[mt][nt][r] = 0.f;

    const int NPAIRS = (K / BK) / 2;  // 32 pairs of K-chunks

    // per-thread invariant addressing
    const int rowA  = wm * 32 + (lane & 15);
    const int halfA = lane >> 4;
    const int swzA  = rowA & 7;
    const int rowB0 = wn * 64 + (lane & 15);
    const int swzB  = lane & 7;

    // prologue: load all 4 stages (chunks 0..3) as two pair-groups
    load_stage_bf16(smem_base, 0, 0, m_base, n_base, K, tid);
    load_stage_bf16(smem_base, 1, 1, m_base, n_base, K, tid);
    cp_commit();                                          // G0 = pair 0
    load_stage_bf16(smem_base, 2, 2, m_base, n_base, K, tid);
    load_stage_bf16(smem_base, 3, 3, m_base, n_base, K, tid);
    cp_commit();                                          // G1 = pair 1

    for (int ip = 0; ip < NPAIRS; ip++) {
        if (ip + 1 < NPAIRS) cp_wait_group<1>();          // pair ip landed
        else                 cp_wait_group<0>();          // drain last pair
        __syncthreads();                                  // visible to all warps

        const int slot0 = (ip & 1) * 2;                   // stages {0,1} or {2,3}

        // compute the two chunks of this pair; warp-rotated ks order to
        // de-synchronize the post-barrier LDSM burst across warps
        #pragma unroll
        for (int half = 0; half < 2; half++) {
            uint32_t a_base = smem_base + (slot0 + half) * STAGE_BYTES;
            uint32_t b_base = a_base + AS_BYTES;
            #pragma unroll
            for (int ks = 0; ks < 4; ks++) {
                const int kk = (ks + wid) & 3;            // rotated k16 step
                uint32_t bq[4][4];
                #pragma unroll
                for (int nq = 0; nq < 4; nq++)
                    ldsm4(bq[nq][0], bq[nq][1], bq[nq][2], bq[nq][3],
                          b_base + (rowB0 + nq * 16) * 128 +
                          (((2 * kk + halfA) ^ swzB) * 16));
                #pragma unroll
                for (int mt = 0; mt < 2; mt++) {
                    uint32_t a[4];
                    ldsm4(a[0], a[1], a[2], a[3],
                          a_base + (rowA + mt * 16) * 128 +
                          (((2 * kk + halfA) ^ swzA) * 16));
                    #pragma unroll
                    for (int nq = 0; nq < 4; nq++) {
                        hmma16816(acc[mt][nq * 2 + 0], a, bq[nq][0], bq[nq][2]);
                        hmma16816(acc[mt][nq * 2 + 1], a, bq[nq][1], bq[nq][3]);
                    }
                }
            }
        }

        __syncthreads();                                  // pair ip fully consumed
        if (ip + 2 < NPAIRS) {
            int kc = (ip + 2) * 2;                        // overwrite pair-ip slots
            load_stage_bf16(smem_base, slot0,     kc,     m_base, n_base, K, tid);
            load_stage_bf16(smem_base, slot0 + 1, kc + 1, m_base, n_base, K, tid);
        }
        cp_commit();                                      // one group per pair
    }

    // ---------------- epilogue ----------------
    #pragma unroll
    for (int mt = 0; mt < 2; mt++) {
        #pragma unroll
        for (int p = 0; p < 2; p++) {
            int m = m_base + wm * 32 + mt * 16 + (lane >> 2) + p * 8;
            float cs = g_xs[m];
            float* orow = out + (size_t)m * N + n_base + wn * 64;
            #pragma unroll
            for (int nt = 0; nt < 8; nt++) {
                int nc = nt * 8 + (lane & 3) * 2;
                int n  = n_base + wn * 64 + nc;
                float2 o;
                o.x = acc[mt][nt][p * 2 + 0] * (cs * g_ws[n + 0]) + bias[n + 0];
                o.y = acc[mt][nt][p * 2 + 1] * (cs * g_ws[n + 1]) + bias[n + 1];
                *reinterpret_cast<float2*>(orow + nc) = o;
            }
        }
    }
}

// ---------------- launcher ----------------
extern "C" void kernel_launch(void* const* d_in, const int* in_sizes, int n_in,
                              void* d_out, int out_size) {
    const float* x    = (const float*)d_in[0];
    const float* w    = (const float*)d_in[1];
    const float* bias = (const float*)d_in[2];
    int N = in_sizes[2];                  // 4096
    int K = in_sizes[1] / N;              // 4096
    int M = in_sizes[0] / K;              // 8192

    quant_fused_kernel<<<N + M, 256>>>(w, x, K, N);

    cudaFuncSetAttribute(qgemm_kernel, cudaFuncAttributeMaxDynamicSharedMemorySize,
                         GEMM_SMEM);
    dim3 grid(N / BN, M / BM);
    qgemm_kernel<<<grid, 512, GEMM_SMEM>>>(bias, (float*)d_out, M, N, K);
}